// round 4
// baseline (speedup 1.0000x reference)
#include <cuda_runtime.h>
#include <cuda_bf16.h>

#define BATCH 16
#define MGT 256
#define NPROP 8192
#define NUM_CLASSES 80
#define KFG 128
#define KBG 384
#define NSAMP 512
#define RADIX_BINS 4096

// Scratch: 45-bit sort keys ((inv_pri<<13)|n) for [fg|bg] x batch x proposals
__device__ unsigned long long g_keys[2ULL * BATCH * NPROP];

// ---------------------------------------------------------------------------
// Kernel A: per-proposal max-IoU match. 4 proposals/thread, division-free
// argmax over (inter, S=areaG+areaP): i1/(S1-i1) > i2/(S2-i2)  <=>  i1*S2 > i2*S1.
// ---------------------------------------------------------------------------
__global__ __launch_bounds__(256)
void iou_match_kernel(const float4* __restrict__ gt_boxes,
                      const float4* __restrict__ prop_boxes,
                      const float* __restrict__ rand_priority,
                      float* __restrict__ out)
{
    __shared__ float4 sg[MGT];
    __shared__ float sarea[MGT];

    const int b   = blockIdx.y;
    const int tid = threadIdx.x;

    {
        float4 g = gt_boxes[b * MGT + tid];
        sg[tid] = g;
        sarea[tid] = (g.z - g.x) * (g.w - g.y);
    }
    __syncthreads();

    const int nb = blockIdx.x * 1024 + tid;

    float4 p[4]; float ap[4];
    float bi[4], bS[4]; int bm[4];
#pragma unroll
    for (int q = 0; q < 4; q++) {
        p[q]  = prop_boxes[b * NPROP + nb + 256 * q];
        ap[q] = (p[q].z - p[q].x) * (p[q].w - p[q].y);
        bi[q] = -1.0f; bS[q] = 1.0f; bm[q] = 0;
    }

#pragma unroll 4
    for (int m = 0; m < MGT; m++) {
        float4 g = sg[m];
        float ga = sarea[m];
#pragma unroll
        for (int q = 0; q < 4; q++) {
            float w = fmaxf(fminf(g.z, p[q].z) - fmaxf(g.x, p[q].x), 0.0f);
            float h = fmaxf(fminf(g.w, p[q].w) - fmaxf(g.y, p[q].y), 0.0f);
            float inter = w * h;
            float S = ga + ap[q];
            // inter/(S-inter) > bi/(bS-bi)  <=>  inter*bS > bi*S  (unions > 0)
            if (inter * bS[q] > bi[q] * S) { bi[q] = inter; bS[q] = S; bm[q] = m; }
        }
    }

    const float* pri_row = rand_priority + b * NPROP;
    unsigned long long* fg_keys = g_keys + (size_t)b * NPROP;
    unsigned long long* bg_keys = g_keys + (size_t)(BATCH + b) * NPROP;

#pragma unroll
    for (int q = 0; q < 4; q++) {
        int n = nb + 256 * q;
        float val = bi[q] / (bS[q] - bi[q]);   // == inter/union, same association as ref

        out[b * NPROP + n] = val;                          // matched_vals
        out[BATCH * NPROP + b * NPROP + n] = (float)bm[q]; // matched_idxs

        unsigned int pu = __float_as_uint(pri_row[n]);
        pu = (pu & 0x80000000u) ? ~pu : (pu | 0x80000000u); // order-preserving
        unsigned int inv = ~pu;                              // descending priority
        bool fg = (val >= 0.5f);

        unsigned long long live   = ((unsigned long long)inv << 13) | (unsigned long long)n;
        unsigned long long masked = (0xFFFFFFFFULL << 13)           | (unsigned long long)n;

        fg_keys[n] = fg ? live : masked;
        bg_keys[n] = fg ? masked : live;
    }
}

// ---------------------------------------------------------------------------
// Kernel B: exact top-k. One (usually) radix round to localize the k-th key,
// rank-by-counting for the in-bin threshold, then rank-by-counting again to
// emit the final k winners in sorted order. No bitonic sorts, ~10 barriers.
// ---------------------------------------------------------------------------
__global__ __launch_bounds__(1024)
void select_kernel(const int* __restrict__ gt_classes,
                   float* __restrict__ out)
{
    __shared__ unsigned int hist[RADIX_BINS];
    __shared__ unsigned int warp_pref[32];
    __shared__ unsigned long long cand[NSAMP];
    __shared__ int sel_bin;
    __shared__ unsigned int sel_excl;
    __shared__ unsigned int s_cnt;
    __shared__ unsigned long long s_thresh;

    const int b = blockIdx.x;      // batch
    const int s = blockIdx.y;      // 0=fg, 1=bg
    const int tid  = threadIdx.x;
    const int lane = tid & 31;
    const int wid  = tid >> 5;

    const unsigned long long* keys = g_keys + ((size_t)s * BATCH + b) * NPROP;

    unsigned long long k64[8];
#pragma unroll
    for (int j = 0; j < 8; j++) k64[j] = keys[tid + j * 1024];

    const unsigned int ksel = (s == 0) ? KFG : KBG;
    unsigned int kk = ksel;                    // rank wanted within survivors (1-indexed)
    unsigned long long prefix = 0, mask = 0;
    unsigned int bincnt = 0;

    for (int r = 0; r < 4; r++) {
        const int shift = (r < 3) ? (33 - 12 * r) : 0;
        const unsigned long long digmask = (r < 3) ? 4095ULL : 511ULL;

#pragma unroll
        for (int i = tid; i < RADIX_BINS; i += 1024) hist[i] = 0;
        __syncthreads();

#pragma unroll
        for (int j = 0; j < 8; j++) {
            if ((k64[j] & mask) == prefix)
                atomicAdd(&hist[(unsigned int)((k64[j] >> shift) & digmask)], 1u);
        }
        __syncthreads();

        // block-wide exclusive scan over 4096 bins (4 per thread)
        unsigned int h0 = hist[4 * tid + 0];
        unsigned int h1 = hist[4 * tid + 1];
        unsigned int h2 = hist[4 * tid + 2];
        unsigned int h3 = hist[4 * tid + 3];
        unsigned int lsum = h0 + h1 + h2 + h3;

        unsigned int x = lsum;
#pragma unroll
        for (int o = 1; o < 32; o <<= 1) {
            unsigned int y = __shfl_up_sync(0xFFFFFFFFu, x, o);
            if (lane >= o) x += y;
        }
        if (lane == 31) warp_pref[wid] = x;
        __syncthreads();
        if (wid == 0) {
            unsigned int v = warp_pref[lane];
            unsigned int xx = v;
#pragma unroll
            for (int o = 1; o < 32; o <<= 1) {
                unsigned int y = __shfl_up_sync(0xFFFFFFFFu, xx, o);
                if (lane >= o) xx += y;
            }
            warp_pref[lane] = xx - v;
        }
        __syncthreads();

        unsigned int e = warp_pref[wid] + (x - lsum);
        unsigned int e0 = e, e1 = e + h0, e2 = e1 + h1, e3 = e2 + h2;
        if (kk > e0 && kk <= e0 + h0) { sel_bin = 4 * tid + 0; sel_excl = e0; }
        if (kk > e1 && kk <= e1 + h1) { sel_bin = 4 * tid + 1; sel_excl = e1; }
        if (kk > e2 && kk <= e2 + h2) { sel_bin = 4 * tid + 2; sel_excl = e2; }
        if (kk > e3 && kk <= e3 + h3) { sel_bin = 4 * tid + 3; sel_excl = e3; }
        __syncthreads();

        prefix |= ((unsigned long long)sel_bin) << shift;
        mask   |= digmask << shift;
        kk     -= sel_excl;
        bincnt  = hist[sel_bin];
        __syncthreads();           // hist read must complete before next-round zeroing

        if (bincnt <= NSAMP) break;   // survivors fit in cand[] -> finish by counting
        // masked-key case: round 2 bins cover <=512 indices each, so we always break by r=2
    }

    // ---- compact survivors (exactly bincnt <= 512 keys with this prefix) ----
    if (tid == 0) s_cnt = 0;
    __syncthreads();
#pragma unroll
    for (int j = 0; j < 8; j++) {
        if ((k64[j] & mask) == prefix) {
            unsigned int pos = atomicAdd(&s_cnt, 1u);
            cand[pos] = k64[j];
        }
    }
    __syncthreads();
    const unsigned int cnt = s_cnt;

    // ---- kk-th smallest survivor by rank counting (keys unique) ----
    if (tid < (int)cnt) {
        unsigned long long xk = cand[tid];
        unsigned int c = 0;
        for (unsigned int j = 0; j < cnt; j++) c += (cand[j] < xk);
        if (c == kk - 1) s_thresh = xk;
    }
    __syncthreads();
    const unsigned long long thresh = s_thresh;

    // ---- global compact: exactly ksel keys <= thresh ----
    if (tid == 0) s_cnt = 0;
    __syncthreads();
#pragma unroll
    for (int j = 0; j < 8; j++) {
        if (k64[j] <= thresh) {
            unsigned int pos = atomicAdd(&s_cnt, 1u);
            cand[pos] = k64[j];
        }
    }
    __syncthreads();

    // ---- rank = output slot; emit directly (ascending key == top_k order) ----
    const int off = (s == 0) ? 0 : KFG;
    if (tid < (int)ksel) {
        unsigned long long xk = cand[tid];
        unsigned int rank = 0;
        for (unsigned int j = 0; j < ksel; j++) rank += (cand[j] < xk);

        int n = (int)(xk & (unsigned long long)(NPROP - 1));
        bool valid = ((unsigned int)(xk >> 13)) != 0xFFFFFFFFu;

        float val = out[b * NPROP + n];
        int midx  = (int)out[BATCH * NPROP + b * NPROP + n];
        int cls   = (val >= 0.5f) ? gt_classes[b * MGT + midx] : NUM_CLASSES;

        const int base = 2 * BATCH * NPROP;
        const int slot = b * NSAMP + off + (int)rank;
        out[base + slot]                     = (float)n;                     // sampled_idxs
        out[base + BATCH * NSAMP + slot]     = valid ? (float)cls  : -1.0f;  // sampled_classes
        out[base + 2 * BATCH * NSAMP + slot] = valid ? (float)midx : -1.0f;  // sampled_gt
    }
}

// ---------------------------------------------------------------------------
extern "C" void kernel_launch(void* const* d_in, const int* in_sizes, int n_in,
                              void* d_out, int out_size)
{
    const float4* gt_boxes   = (const float4*)d_in[0];
    const int*    gt_classes = (const int*)  d_in[1];
    const float4* prop_boxes = (const float4*)d_in[2];
    const float*  rand_pri   = (const float*)d_in[3];
    float* out = (float*)d_out;

    (void)in_sizes; (void)n_in; (void)out_size;

    dim3 gridA(NPROP / 1024, BATCH);
    iou_match_kernel<<<gridA, 256>>>(gt_boxes, prop_boxes, rand_pri, out);

    dim3 gridB(BATCH, 2);
    select_kernel<<<gridB, 1024>>>(gt_classes, out);
}